// round 3
// baseline (speedup 1.0000x reference)
#include <cuda_runtime.h>
#include <cuda_bf16.h>

#define NUM_HIST 4

__device__ __forceinline__ float reluf(float x) { return x > 0.0f ? x : 0.0f; }

// overlap(): min of relu'd signed distances to box faces (LONG_T = LAT_T = 0)
__device__ __forceinline__ float overlap(float lx, float ly,
                                         float f, float r, float l, float rt) {
    float a = fminf(reluf(f - lx), reluf(r + lx));
    float b = fminf(reluf(l - ly), reluf(rt + ly));
    return fminf(a, b);
}

// One block per (t, e). Scan all n, filter by batch/ego/validity, compute
// pairwise overlap loss, OR-reduce "any edge" and "any loss > 0".
// msk is read as 32-bit words and tested != 0: correct for both int32 {0,1}
// and float32 {0.0f, 1.0f} encodings of the original bool array.
__global__ void done_kernel(const float* __restrict__ pos,          // (N, T_TOT, 2)
                            const float* __restrict__ yaw,          // (N, T_TOT)
                            const unsigned int* __restrict__ msk,   // (N, T_TOT)
                            const float* __restrict__ box,          // (N, 4)
                            const int* __restrict__ batch,          // (N,)
                            const int* __restrict__ ego,            // (Ne,)
                            float* __restrict__ out,                // done at [e*T + t]
                            int N, int T_TOT, int T, int Ne)
{
    const int t  = blockIdx.x;          // 0..T-1
    const int e  = blockIdx.y;          // 0..Ne-1
    const int tt = t + NUM_HIST;

    const int ei = ego[e];
    const int eb = batch[ei];

    const float eyaw = yaw[ei * T_TOT + tt];
    const float ex   = pos[(ei * T_TOT + tt) * 2 + 0];
    const float ey   = pos[(ei * T_TOT + tt) * 2 + 1];
    const unsigned int emv = msk[ei * T_TOT + tt];
    const float ef  = box[ei * 4 + 0];
    const float er  = box[ei * 4 + 1];
    const float el  = box[ei * 4 + 2];
    const float ert = box[ei * 4 + 3];

    const float ce = cosf(eyaw), se = sinf(eyaw);

    // ego corner positions (global frame)
    float ecx[4], ecy[4];
    {
        const float lx[4] = { ef,  ef, -er, -er };
        const float ly[4] = { el, -ert, -ert, el };
#pragma unroll
        for (int c = 0; c < 4; c++) {
            ecx[c] = ex + ce * lx[c] - se * ly[c];
            ecy[c] = ey + se * lx[c] + ce * ly[c];
        }
    }

    int any_edge = 0;
    int any_hit  = 0;

    if (emv != 0u) {
        for (int n = threadIdx.x; n < N; n += blockDim.x) {
            if (batch[n] != eb || n == ei)    continue;
            if (msk[n * T_TOT + tt] == 0u)    continue;
            any_edge = 1;

            const float nyaw = yaw[n * T_TOT + tt];
            const float nx   = pos[(n * T_TOT + tt) * 2 + 0];
            const float ny   = pos[(n * T_TOT + tt) * 2 + 1];
            const float nf   = box[n * 4 + 0];
            const float nr   = box[n * 4 + 1];
            const float nl   = box[n * 4 + 2];
            const float nrt  = box[n * 4 + 3];
            const float cn = cosf(nyaw), sn = sinf(nyaw);

            // A: ego corners in agent-n frame, overlap vs agent box
            float A = 0.0f;
#pragma unroll
            for (int c = 0; c < 4; c++) {
                float dx = ecx[c] - nx;
                float dy = ecy[c] - ny;
                float alx =  cn * dx + sn * dy;
                float aly = -sn * dx + cn * dy;
                A = fmaxf(A, overlap(alx, aly, nf, nr, nl, nrt));
            }

            // B: agent-n corners in ego frame, overlap vs ego box
            float B = 0.0f;
            {
                const float lx[4] = { nf,  nf, -nr, -nr };
                const float ly[4] = { nl, -nrt, -nrt, nl };
#pragma unroll
                for (int c = 0; c < 4; c++) {
                    float cxg = nx + cn * lx[c] - sn * ly[c];
                    float cyg = ny + sn * lx[c] + cn * ly[c];
                    float dx = cxg - ex;
                    float dy = cyg - ey;
                    float blx =  ce * dx + se * dy;
                    float bly = -se * dx + ce * dy;
                    B = fmaxf(B, overlap(blx, bly, ef, er, el, ert));
                }
            }

            if (fmaxf(A, B) > 0.0f) any_hit = 1;
        }
    }

    int blk_edge = __syncthreads_or(any_edge);
    int blk_hit  = __syncthreads_or(any_hit);

    if (threadIdx.x == 0) {
        // done.T layout: [e, t]
        out[e * T + t] = (blk_edge && blk_hit) ? 1.0f : 0.0f;
    }
}

// reward[e] = all_t( !done[t,e] )
__global__ void reward_kernel(float* __restrict__ out, int T, int Ne)
{
    int e = blockIdx.x * blockDim.x + threadIdx.x;
    if (e >= Ne) return;
    float r = 1.0f;
    for (int t = 0; t < T; t++) {
        if (out[e * T + t] != 0.0f) r = 0.0f;
    }
    out[Ne * T + e] = r;
}

extern "C" void kernel_launch(void* const* d_in, const int* in_sizes, int n_in,
                              void* d_out, int out_size)
{
    const float*        pos   = (const float*)d_in[0];         // (N, T_TOT, 2)
    const float*        yaw   = (const float*)d_in[1];         // (N, T_TOT)
    const unsigned int* msk   = (const unsigned int*)d_in[2];  // (N, T_TOT) bool as 32-bit
    const float*        box   = (const float*)d_in[3];         // (N, 4)
    const int*          batch = (const int*)d_in[4];           // (N,)
    const int*          ego   = (const int*)d_in[5];           // (Ne,)
    float*              out   = (float*)d_out;

    const int N     = in_sizes[4];
    const int T_TOT = in_sizes[1] / N;
    const int T     = T_TOT - NUM_HIST;
    const int Ne    = in_sizes[5];

    dim3 grid(T, Ne);
    done_kernel<<<grid, 128>>>(pos, yaw, msk, box, batch, ego, out,
                               N, T_TOT, T, Ne);
    reward_kernel<<<(Ne + 63) / 64, 64>>>(out, T, Ne);
}

// round 4
// speedup vs baseline: 1.3761x; 1.3761x over previous
#include <cuda_runtime.h>
#include <cuda_bf16.h>

#define NUM_HIST 4

__device__ __forceinline__ float reluf(float x) { return x > 0.0f ? x : 0.0f; }

// overlap(): min of relu'd signed distances to box faces (LONG_T = LAT_T = 0)
__device__ __forceinline__ float overlap(float lx, float ly,
                                         float f, float r, float l, float rt) {
    float a = fminf(reluf(f - lx), reluf(r + lx));
    float b = fminf(reluf(l - ly), reluf(rt + ly));
    return fminf(a, b);
}

// Fused kernel: one block per ego e, one warp per timestep t.
// batch[] is non-decreasing, so agents sharing ego's batch form a contiguous
// range [lo, hi) found by binary search once per block. Each warp scans only
// that range (~64 agents), ballots "any edge" / "any hit", writes done[e*T+t],
// and thread 0 folds the per-t results into reward[e]. Single launch.
__global__ void fused_kernel(const float* __restrict__ pos,          // (N, T_TOT, 2)
                             const float* __restrict__ yaw,          // (N, T_TOT)
                             const unsigned int* __restrict__ msk,   // (N, T_TOT) bool as 32-bit
                             const float* __restrict__ box,          // (N, 4)
                             const int* __restrict__ batch,          // (N,) sorted
                             const int* __restrict__ ego,            // (Ne,)
                             float* __restrict__ out,                // [done.T | reward]
                             int N, int T_TOT, int T, int Ne)
{
    const int e    = blockIdx.x;
    const int t    = threadIdx.x >> 5;   // warp id == timestep
    const int lane = threadIdx.x & 31;

    __shared__ int   s_lo, s_hi;
    __shared__ float sdone[32];

    const int ei = ego[e];
    const int eb = batch[ei];

    if (threadIdx.x == 0) {
        // lower_bound / upper_bound of eb in sorted batch[]
        int lo = 0, hi = N;
        while (lo < hi) { int m = (lo + hi) >> 1; if (batch[m] <  eb) lo = m + 1; else hi = m; }
        s_lo = lo;
        hi = N;
        while (lo < hi) { int m = (lo + hi) >> 1; if (batch[m] <= eb) lo = m + 1; else hi = m; }
        s_hi = lo;
    }
    __syncthreads();
    const int lo = s_lo, hi = s_hi;

    if (t < T) {
        const int tt = t + NUM_HIST;

        const float eyaw = yaw[ei * T_TOT + tt];
        const float ex   = pos[(ei * T_TOT + tt) * 2 + 0];
        const float ey   = pos[(ei * T_TOT + tt) * 2 + 1];
        const unsigned int emv = msk[ei * T_TOT + tt];
        const float ef  = box[ei * 4 + 0];
        const float er  = box[ei * 4 + 1];
        const float el  = box[ei * 4 + 2];
        const float ert = box[ei * 4 + 3];

        const float ce = cosf(eyaw), se = sinf(eyaw);

        // ego corner positions (global frame)
        float ecx[4], ecy[4];
        {
            const float lx[4] = { ef,  ef, -er, -er };
            const float ly[4] = { el, -ert, -ert, el };
#pragma unroll
            for (int c = 0; c < 4; c++) {
                ecx[c] = ex + ce * lx[c] - se * ly[c];
                ecy[c] = ey + se * lx[c] + ce * ly[c];
            }
        }

        int any_edge = 0;
        int any_hit  = 0;

        if (emv != 0u) {
            for (int n = lo + lane; n < hi; n += 32) {
                if (n == ei)                   continue;
                if (msk[n * T_TOT + tt] == 0u) continue;
                any_edge = 1;

                const float nyaw = yaw[n * T_TOT + tt];
                const float nx   = pos[(n * T_TOT + tt) * 2 + 0];
                const float ny   = pos[(n * T_TOT + tt) * 2 + 1];
                const float nf   = box[n * 4 + 0];
                const float nr   = box[n * 4 + 1];
                const float nl   = box[n * 4 + 2];
                const float nrt  = box[n * 4 + 3];
                const float cn = cosf(nyaw), sn = sinf(nyaw);

                // A: ego corners in agent-n frame, overlap vs agent box
                float A = 0.0f;
#pragma unroll
                for (int c = 0; c < 4; c++) {
                    float dx = ecx[c] - nx;
                    float dy = ecy[c] - ny;
                    float alx =  cn * dx + sn * dy;
                    float aly = -sn * dx + cn * dy;
                    A = fmaxf(A, overlap(alx, aly, nf, nr, nl, nrt));
                }

                // B: agent-n corners in ego frame, overlap vs ego box
                float B = 0.0f;
                {
                    const float lx[4] = { nf,  nf, -nr, -nr };
                    const float ly[4] = { nl, -nrt, -nrt, nl };
#pragma unroll
                    for (int c = 0; c < 4; c++) {
                        float cxg = nx + cn * lx[c] - sn * ly[c];
                        float cyg = ny + sn * lx[c] + cn * ly[c];
                        float dx = cxg - ex;
                        float dy = cyg - ey;
                        float blx =  ce * dx + se * dy;
                        float bly = -se * dx + ce * dy;
                        B = fmaxf(B, overlap(blx, bly, ef, er, el, ert));
                    }
                }

                if (fmaxf(A, B) > 0.0f) any_hit = 1;
            }
        }

        const unsigned be = __ballot_sync(0xffffffffu, any_edge);
        const unsigned bh = __ballot_sync(0xffffffffu, any_hit);
        const float d = (be != 0u && bh != 0u) ? 1.0f : 0.0f;
        if (lane == 0) {
            out[e * T + t] = d;   // done.T layout: [e, t]
            sdone[t] = d;
        }
    }
    __syncthreads();

    if (threadIdx.x == 0) {
        float r = 1.0f;
        for (int k = 0; k < T; k++) {
            if (sdone[k] != 0.0f) r = 0.0f;
        }
        out[Ne * T + e] = r;
    }
}

extern "C" void kernel_launch(void* const* d_in, const int* in_sizes, int n_in,
                              void* d_out, int out_size)
{
    const float*        pos   = (const float*)d_in[0];         // (N, T_TOT, 2)
    const float*        yaw   = (const float*)d_in[1];         // (N, T_TOT)
    const unsigned int* msk   = (const unsigned int*)d_in[2];  // (N, T_TOT) bool as 32-bit
    const float*        box   = (const float*)d_in[3];         // (N, 4)
    const int*          batch = (const int*)d_in[4];           // (N,)
    const int*          ego   = (const int*)d_in[5];           // (Ne,)
    float*              out   = (float*)d_out;

    const int N     = in_sizes[4];
    const int T_TOT = in_sizes[1] / N;
    const int T     = T_TOT - NUM_HIST;   // 16
    const int Ne    = in_sizes[5];        // 64

    fused_kernel<<<Ne, 32 * T>>>(pos, yaw, msk, box, batch, ego, out,
                                 N, T_TOT, T, Ne);
}

// round 5
// speedup vs baseline: 1.5475x; 1.1246x over previous
#include <cuda_runtime.h>
#include <cuda_bf16.h>

#define NUM_HIST 4

__device__ __forceinline__ float reluf(float x) { return x > 0.0f ? x : 0.0f; }

// overlap(): min of relu'd signed distances to box faces (LONG_T = LAT_T = 0)
__device__ __forceinline__ float overlap(float lx, float ly,
                                         float f, float r, float l, float rt) {
    float a = fminf(reluf(f - lx), reluf(r + lx));
    float b = fminf(reluf(l - ly), reluf(rt + ly));
    return fminf(a, b);
}

// Fused single-launch kernel: one block per ego e, one warp per timestep t.
// batch[] is non-decreasing, so agents sharing ego's batch form a contiguous
// range. The range is found by a fully parallel strided probe of batch[]
// (all 512 threads, coalesced, one memory round-trip) + smem atomicMin/Max,
// instead of a serial binary search. Each warp then scans only that range,
// with unconditional (predicated-result) loads so the 8 loads per candidate
// issue back-to-back and overlap their latency.
__global__ void fused_kernel(const float* __restrict__ pos,          // (N, T_TOT, 2)
                             const float* __restrict__ yaw,          // (N, T_TOT)
                             const unsigned int* __restrict__ msk,   // (N, T_TOT) bool as 32-bit
                             const float* __restrict__ box,          // (N, 4)
                             const int* __restrict__ batch,          // (N,) sorted
                             const int* __restrict__ ego,            // (Ne,)
                             float* __restrict__ out,                // [done.T | reward]
                             int N, int T_TOT, int T, int Ne)
{
    const int e    = blockIdx.x;
    const int t    = threadIdx.x >> 5;   // warp id == timestep
    const int lane = threadIdx.x & 31;

    __shared__ int   s_lo, s_hi;
    __shared__ float sdone[32];

    const int ei = ego[e];
    const int eb = batch[ei];

    if (threadIdx.x == 0) { s_lo = N; s_hi = 0; }
    __syncthreads();

    // Parallel range-find: every thread probes a strided, coalesced slice of
    // batch[]; matching indices shrink [s_lo, s_hi) via smem atomics.
    for (int n = threadIdx.x; n < N; n += blockDim.x) {
        if (batch[n] == eb) {
            atomicMin(&s_lo, n);
            atomicMax(&s_hi, n + 1);
        }
    }
    __syncthreads();
    const int lo = s_lo, hi = s_hi;

    if (t < T) {
        const int tt = t + NUM_HIST;

        const float eyaw = yaw[ei * T_TOT + tt];
        const float ex   = pos[(ei * T_TOT + tt) * 2 + 0];
        const float ey   = pos[(ei * T_TOT + tt) * 2 + 1];
        const unsigned int emv = msk[ei * T_TOT + tt];
        const float ef  = box[ei * 4 + 0];
        const float er  = box[ei * 4 + 1];
        const float el  = box[ei * 4 + 2];
        const float ert = box[ei * 4 + 3];

        float ce, se;
        sincosf(eyaw, &se, &ce);

        // ego corner positions (global frame)
        float ecx[4], ecy[4];
        {
            const float lx[4] = { ef,  ef, -er, -er };
            const float ly[4] = { el, -ert, -ert, el };
#pragma unroll
            for (int c = 0; c < 4; c++) {
                ecx[c] = ex + ce * lx[c] - se * ly[c];
                ecy[c] = ey + se * lx[c] + ce * ly[c];
            }
        }

        int any_edge = 0;
        int any_hit  = 0;

        if (emv != 0u) {
            for (int n = lo + lane; n < hi; n += 32) {
                // Unconditional loads: 8 independent addresses, issued together.
                const unsigned int nmv = msk[n * T_TOT + tt];
                const float nyaw = yaw[n * T_TOT + tt];
                const float nx   = pos[(n * T_TOT + tt) * 2 + 0];
                const float ny   = pos[(n * T_TOT + tt) * 2 + 1];
                const float nf   = box[n * 4 + 0];
                const float nr   = box[n * 4 + 1];
                const float nl   = box[n * 4 + 2];
                const float nrt  = box[n * 4 + 3];

                const bool valid = (nmv != 0u) && (n != ei);
                any_edge |= valid ? 1 : 0;

                float cn, sn;
                sincosf(nyaw, &sn, &cn);

                // A: ego corners in agent-n frame, overlap vs agent box
                float A = 0.0f;
#pragma unroll
                for (int c = 0; c < 4; c++) {
                    float dx = ecx[c] - nx;
                    float dy = ecy[c] - ny;
                    float alx =  cn * dx + sn * dy;
                    float aly = -sn * dx + cn * dy;
                    A = fmaxf(A, overlap(alx, aly, nf, nr, nl, nrt));
                }

                // B: agent-n corners in ego frame, overlap vs ego box
                float B = 0.0f;
                {
                    const float lx[4] = { nf,  nf, -nr, -nr };
                    const float ly[4] = { nl, -nrt, -nrt, nl };
#pragma unroll
                    for (int c = 0; c < 4; c++) {
                        float cxg = nx + cn * lx[c] - sn * ly[c];
                        float cyg = ny + sn * lx[c] + cn * ly[c];
                        float dx = cxg - ex;
                        float dy = cyg - ey;
                        float blx =  ce * dx + se * dy;
                        float bly = -se * dx + ce * dy;
                        B = fmaxf(B, overlap(blx, bly, ef, er, el, ert));
                    }
                }

                any_hit |= (valid && fmaxf(A, B) > 0.0f) ? 1 : 0;
            }
        }

        const unsigned be = __ballot_sync(0xffffffffu, any_edge);
        const unsigned bh = __ballot_sync(0xffffffffu, any_hit);
        const float d = (be != 0u && bh != 0u) ? 1.0f : 0.0f;
        if (lane == 0) {
            out[e * T + t] = d;   // done.T layout: [e, t]
            sdone[t] = d;
        }
    }
    __syncthreads();

    if (threadIdx.x == 0) {
        float r = 1.0f;
        for (int k = 0; k < T; k++) {
            if (sdone[k] != 0.0f) r = 0.0f;
        }
        out[Ne * T + e] = r;
    }
}

extern "C" void kernel_launch(void* const* d_in, const int* in_sizes, int n_in,
                              void* d_out, int out_size)
{
    const float*        pos   = (const float*)d_in[0];         // (N, T_TOT, 2)
    const float*        yaw   = (const float*)d_in[1];         // (N, T_TOT)
    const unsigned int* msk   = (const unsigned int*)d_in[2];  // (N, T_TOT) bool as 32-bit
    const float*        box   = (const float*)d_in[3];         // (N, 4)
    const int*          batch = (const int*)d_in[4];           // (N,)
    const int*          ego   = (const int*)d_in[5];           // (Ne,)
    float*              out   = (float*)d_out;

    const int N     = in_sizes[4];
    const int T_TOT = in_sizes[1] / N;
    const int T     = T_TOT - NUM_HIST;   // 16
    const int Ne    = in_sizes[5];        // 64

    fused_kernel<<<Ne, 32 * T>>>(pos, yaw, msk, box, batch, ego, out,
                                 N, T_TOT, T, Ne);
}